// round 13
// baseline (speedup 1.0000x reference)
#include <cuda_runtime.h>
#include <cstdint>

// QualityAwarePatchAugment — GB300 sm_103a — R9.
// One block = TWO horizontally adjacent patches (pA=2bx, pB=pA+1), which share
// the same 128B cache lines (a patch row is 64B). A is processed from a
// register cache (LDG.128 x8, MLP anchor); B is simultaneously cp.async'd
// into smem (zero landing regs, L1/L2 hits since A's LDGs fetched the lines).
// While A is reduced/applied, B's copies stream; B's processing then has no
// DRAM load dependency at all. Two barriers per 64KB instead of one per 32KB,
// and B's store stretch overlaps other blocks' load bursts.

__device__ __forceinline__ float clipf(float v) {
    return fminf(fmaxf(v, 0.0f), 1.0f);
}

__device__ __forceinline__ void cp16(uint32_t smem_dst, const void* gptr) {
    asm volatile("cp.async.cg.shared.global [%0], [%1], 16;"
                 :: "r"(smem_dst), "l"(gptr));
}

// Decide per-patch action from q and the 8 prefetched scalars.
__device__ __forceinline__ int decide(float q, const float* sc, float& param) {
    const bool low    = q < 0.7f;
    const bool strong = low && (sc[0] < 0.8f);
    const bool drop   = low && (q < 0.3f) && (sc[1] < 0.1f);
    const bool els    = (!low) && (sc[2] < 0.3f);
    int code = 0;
    if (strong) code = __float_as_int(sc[6]) + 1;   // aug_choice + 1
    if (els)    code = __float_as_int(sc[7]) + 5;   // slight_choice + 5
    if (drop)   code = 7;
    param = 0.0f;
    switch (code) {
        case 1: param = 0.1f;   break;
        case 3: param = sc[3];  break;   // bright_f
        case 4: param = sc[4];  break;   // contrast_f
        case 5: param = 0.05f;  break;
        case 6: param = sc[5];  break;   // slight_f
        default: break;
    }
    return code;
}

// Butterfly fold of 32 per-batch (sum, sumsq) pairs -> (q, mpp) on all lanes.
__device__ __forceinline__ void fold(const float* sh_s, const float* sh_s2,
                                     int lane, float& q, float& mpp) {
    const float bs  = sh_s[lane];
    const float bs2 = sh_s2[lane];
    const float mean = bs * (1.0f / 256.0f);
    float var = (bs2 - bs * bs * (1.0f / 256.0f)) * (1.0f / 255.0f); // ddof=1
    var = fmaxf(var, 0.0f);
    const float sd = sqrtf(var);
    const float iq = 1.0f - 2.0f * fabsf(mean - 0.5f);
    float qs  = (sd + iq + var) * (1.0f / 3.0f);
    float tot = bs;
    #pragma unroll
    for (int off = 16; off; off >>= 1) {
        qs  += __shfl_xor_sync(0xffffffffu, qs,  off);
        tot += __shfl_xor_sync(0xffffffffu, tot, off);
    }
    q   = qs  * (1.0f / 32.0f);
    mpp = tot * (1.0f / 8192.0f);           // 32 batches * 256 px
}

__global__ void __launch_bounds__(256, 4) fused_kernel(
    const float4* __restrict__ img,
    const float4* __restrict__ noise,
    float4*       __restrict__ out,
    const float*  __restrict__ r_strong,
    const float*  __restrict__ r_drop,
    const float*  __restrict__ r_else,
    const float*  __restrict__ bright_f,
    const float*  __restrict__ contrast_f,
    const float*  __restrict__ slight_f,
    const int*    __restrict__ aug_choice,
    const int*    __restrict__ slight_choice)
{
    __shared__ float smB[32 * 256];         // patch B tile (cp.async target)
    __shared__ float shA_s[32], shA_s2[32];
    __shared__ float shB_s[32], shB_s2[32];
    __shared__ float s_scal[16];            // [0..7]=A, [8..15]=B

    const int bx   = blockIdx.x;
    const int pA   = bx << 1;               // pw even
    const int pB   = pA + 1;                // same rows, next 64B half-lines
    const int ph   = pA >> 6;
    const int pwA  = pA & 63;
    const int t    = threadIdx.x;
    const int b    = t >> 3;                // batch 0..31
    const int l8   = t & 7;
    const int lane = t & 31;

    // Prefetch both patches' decision scalars.
    if (t < 16) {
        const int pp = (t < 8) ? pA : pB;
        float v;
        switch (t & 7) {
            case 0: v = r_strong[pp];                       break;
            case 1: v = r_drop[pp];                         break;
            case 2: v = r_else[pp];                         break;
            case 3: v = bright_f[pp];                       break;
            case 4: v = contrast_f[pp];                     break;
            case 5: v = slight_f[pp];                       break;
            case 6: v = __int_as_float(aug_choice[pp]);     break;
            default: v = __int_as_float(slight_choice[pp]); break;
        }
        s_scal[t] = v;
    }

    // float4 bases of (batch b, row 0); img row stride = 256 float4.
    const int fA = (b << 18) + (ph << 12) + (pwA << 2);
    const int fB = fA + 4;
    float* const smb = smB + (b << 8);
    const uint32_t smb_u = (uint32_t)__cvta_generic_to_shared(smb);

    // ---- Phase 0: A -> registers (DRAM fetch), B -> smem via cp.async -----
    float4 v[8];
    float s = 0.0f, s2 = 0.0f;
    #pragma unroll
    for (int k = 0; k < 8; k++) {
        const int fi = l8 + (k << 3);       // slot 0..63; row=fi>>2, c4=fi&3
        v[k] = img[fA + ((fi >> 2) << 8) + (fi & 3)];
        s  += v[k].x + v[k].y + v[k].z + v[k].w;
        s2 += v[k].x * v[k].x + v[k].y * v[k].y
            + v[k].z * v[k].z + v[k].w * v[k].w;
    }
    #pragma unroll
    for (int k = 0; k < 8; k++) {
        const int fi = l8 + (k << 3);
        cp16(smb_u + ((((fi >> 2) << 4) + ((fi & 3) << 2)) << 2),
             img + fB + ((fi >> 2) << 8) + (fi & 3));
    }
    asm volatile("cp.async.commit_group;");

    #pragma unroll
    for (int off = 4; off; off >>= 1) {
        s  += __shfl_down_sync(0xffffffffu, s,  off, 8);
        s2 += __shfl_down_sync(0xffffffffu, s2, off, 8);
    }
    if (l8 == 0) { shA_s[b] = s; shA_s2[b] = s2; }
    __syncthreads();                        // bar1: A sums ready

    // ---- Patch A: fold, decide, apply from registers ----------------------
    float qA, mppA, paramA;
    fold(shA_s, shA_s2, lane, qA, mppA);
    const int codeA = decide(qA, s_scal, paramA);

    if (codeA == 0) {
        #pragma unroll
        for (int k = 0; k < 8; k++) {
            const int fi = l8 + (k << 3);
            out[fA + ((fi >> 2) << 8) + (fi & 3)] = v[k];
        }
    } else if (codeA == 1 || codeA == 5) {
        #pragma unroll
        for (int k = 0; k < 8; k++) {
            const int fi = l8 + (k << 3);
            const int gi = fA + ((fi >> 2) << 8) + (fi & 3);
            const float4 n = __ldcs(&noise[gi]);
            float4 o;
            o.x = clipf(fmaf(paramA, n.x, v[k].x));
            o.y = clipf(fmaf(paramA, n.y, v[k].y));
            o.z = clipf(fmaf(paramA, n.z, v[k].z));
            o.w = clipf(fmaf(paramA, n.w, v[k].w));
            out[gi] = o;
        }
    } else if (codeA == 2) {                // blur A: neighbors via L1 hits
        const float inv9 = 1.0f / 9.0f;
        const float* imgf = (const float*)img;
        #pragma unroll
        for (int k = 0; k < 8; k++) {
            const int fi  = l8 + (k << 3);
            const int row = fi >> 2;
            const int c4  = fi & 3;
            float a0 = 0.f, a1 = 0.f, a2 = 0.f, a3 = 0.f;
            #pragma unroll
            for (int dr = -1; dr <= 1; dr++) {
                const int r = row + dr;
                if (r < 0 || r > 15) continue;          // zero padding
                const int basef4 = fA + (r << 8) + c4;
                const int basepx = basef4 << 2;
                const float4 vv = img[basef4];          // L1 hit (just loaded)
                const float lft = (c4 > 0) ? __ldg(imgf + basepx - 1) : 0.0f;
                const float rgt = (c4 < 3) ? __ldg(imgf + basepx + 4) : 0.0f;
                a0 += lft  + vv.x + vv.y;
                a1 += vv.x + vv.y + vv.z;
                a2 += vv.y + vv.z + vv.w;
                a3 += vv.z + vv.w + rgt;
            }
            out[fA + (row << 8) + c4] =
                make_float4(a0 * inv9, a1 * inv9, a2 * inv9, a3 * inv9);
        }
    } else if (codeA == 3 || codeA == 6) {
        #pragma unroll
        for (int k = 0; k < 8; k++) {
            const int fi = l8 + (k << 3);
            float4 o;
            o.x = clipf(v[k].x * paramA);
            o.y = clipf(v[k].y * paramA);
            o.z = clipf(v[k].z * paramA);
            o.w = clipf(v[k].w * paramA);
            out[fA + ((fi >> 2) << 8) + (fi & 3)] = o;
        }
    } else if (codeA == 4) {
        #pragma unroll
        for (int k = 0; k < 8; k++) {
            const int fi = l8 + (k << 3);
            float4 o;
            o.x = clipf(fmaf(v[k].x - mppA, paramA, mppA));
            o.y = clipf(fmaf(v[k].y - mppA, paramA, mppA));
            o.z = clipf(fmaf(v[k].z - mppA, paramA, mppA));
            o.w = clipf(fmaf(v[k].w - mppA, paramA, mppA));
            out[fA + ((fi >> 2) << 8) + (fi & 3)] = o;
        }
    } else {                                // drop
        const float4 z = make_float4(0.f, 0.f, 0.f, 0.f);
        #pragma unroll
        for (int k = 0; k < 8; k++) {
            const int fi = l8 + (k << 3);
            out[fA + ((fi >> 2) << 8) + (fi & 3)] = z;
        }
    }

    // ---- Patch B: stats from smem (own slots), fold, apply from smem ------
    asm volatile("cp.async.wait_group 0;" ::: "memory");
    float sB = 0.0f, sB2 = 0.0f;
    #pragma unroll
    for (int k = 0; k < 8; k++) {
        const int fi = l8 + (k << 3);
        const float4 w = *reinterpret_cast<const float4*>(
            smb + ((fi >> 2) << 4) + ((fi & 3) << 2));
        sB  += w.x + w.y + w.z + w.w;
        sB2 += w.x * w.x + w.y * w.y + w.z * w.z + w.w * w.w;
    }
    #pragma unroll
    for (int off = 4; off; off >>= 1) {
        sB  += __shfl_down_sync(0xffffffffu, sB,  off, 8);
        sB2 += __shfl_down_sync(0xffffffffu, sB2, off, 8);
    }
    if (l8 == 0) { shB_s[b] = sB; shB_s2[b] = sB2; }
    __syncthreads();                        // bar2: B sums + B tile visible

    float qB, mppB, paramB;
    fold(shB_s, shB_s2, lane, qB, mppB);
    const int codeB = decide(qB, s_scal + 8, paramB);

    if (codeB == 0) {
        #pragma unroll
        for (int k = 0; k < 8; k++) {
            const int fi = l8 + (k << 3);
            const float4 w = *reinterpret_cast<const float4*>(
                smb + ((fi >> 2) << 4) + ((fi & 3) << 2));
            out[fB + ((fi >> 2) << 8) + (fi & 3)] = w;
        }
    } else if (codeB == 1 || codeB == 5) {
        #pragma unroll
        for (int k = 0; k < 8; k++) {
            const int fi = l8 + (k << 3);
            const int gi = fB + ((fi >> 2) << 8) + (fi & 3);
            const float4 w = *reinterpret_cast<const float4*>(
                smb + ((fi >> 2) << 4) + ((fi & 3) << 2));
            const float4 n = __ldcs(&noise[gi]);
            float4 o;
            o.x = clipf(fmaf(paramB, n.x, w.x));
            o.y = clipf(fmaf(paramB, n.y, w.y));
            o.z = clipf(fmaf(paramB, n.z, w.z));
            o.w = clipf(fmaf(paramB, n.w, w.w));
            out[gi] = o;
        }
    } else if (codeB == 2) {                // blur B from smem
        const float inv9 = 1.0f / 9.0f;
        #pragma unroll
        for (int k = 0; k < 8; k++) {
            const int fi  = l8 + (k << 3);
            const int row = fi >> 2;
            const int c0  = (fi & 3) << 2;
            float a0 = 0.f, a1 = 0.f, a2 = 0.f, a3 = 0.f;
            #pragma unroll
            for (int dr = -1; dr <= 1; dr++) {
                const int r = row + dr;
                if (r < 0 || r > 15) continue;
                const float* rp = smb + (r << 4);
                const float lft = (c0 > 0)  ? rp[c0 - 1] : 0.0f;
                const float rgt = (c0 < 12) ? rp[c0 + 4] : 0.0f;
                const float m0 = rp[c0], m1 = rp[c0 + 1];
                const float m2 = rp[c0 + 2], m3 = rp[c0 + 3];
                a0 += lft + m0 + m1;
                a1 += m0 + m1 + m2;
                a2 += m1 + m2 + m3;
                a3 += m2 + m3 + rgt;
            }
            out[fB + (row << 8) + (fi & 3)] =
                make_float4(a0 * inv9, a1 * inv9, a2 * inv9, a3 * inv9);
        }
    } else if (codeB == 3 || codeB == 6) {
        #pragma unroll
        for (int k = 0; k < 8; k++) {
            const int fi = l8 + (k << 3);
            const float4 w = *reinterpret_cast<const float4*>(
                smb + ((fi >> 2) << 4) + ((fi & 3) << 2));
            float4 o;
            o.x = clipf(w.x * paramB);
            o.y = clipf(w.y * paramB);
            o.z = clipf(w.z * paramB);
            o.w = clipf(w.w * paramB);
            out[fB + ((fi >> 2) << 8) + (fi & 3)] = o;
        }
    } else if (codeB == 4) {
        #pragma unroll
        for (int k = 0; k < 8; k++) {
            const int fi = l8 + (k << 3);
            const float4 w = *reinterpret_cast<const float4*>(
                smb + ((fi >> 2) << 4) + ((fi & 3) << 2));
            float4 o;
            o.x = clipf(fmaf(w.x - mppB, paramB, mppB));
            o.y = clipf(fmaf(w.y - mppB, paramB, mppB));
            o.z = clipf(fmaf(w.z - mppB, paramB, mppB));
            o.w = clipf(fmaf(w.w - mppB, paramB, mppB));
            out[fB + ((fi >> 2) << 8) + (fi & 3)] = o;
        }
    } else {                                // drop
        const float4 z = make_float4(0.f, 0.f, 0.f, 0.f);
        #pragma unroll
        for (int k = 0; k < 8; k++) {
            const int fi = l8 + (k << 3);
            out[fB + ((fi >> 2) << 8) + (fi & 3)] = z;
        }
    }
}

extern "C" void kernel_launch(void* const* d_in, const int* in_sizes, int n_in,
                              void* d_out, int out_size)
{
    fused_kernel<<<2048, 256>>>(
        (const float4*)d_in[0],   // img
        (const float4*)d_in[1],   // noise
        (float4*)d_out,
        (const float*)d_in[2],    // r_strong
        (const float*)d_in[3],    // r_drop
        (const float*)d_in[4],    // r_else
        (const float*)d_in[5],    // bright_f
        (const float*)d_in[6],    // contrast_f
        (const float*)d_in[7],    // slight_f
        (const int*)d_in[8],      // aug_choice
        (const int*)d_in[9]);     // slight_choice
}